// round 8
// baseline (speedup 1.0000x reference)
#include <cuda_runtime.h>
#include <cuda_fp16.h>
#include <cstdint>

// ============================================================================
// Collapse (verified): out = 2048 * x @ (Wp@Wv)^T + (2048*Wp@bv + bp)
// fp16 HMMA path (R6 rel_err 2.9e-4; R7 occupancy -> 106.6us).
// R8: main GEMM warp tile 32x64 -> 64x64 (CTA 256x128, 8 warps, 1 CTA/SM):
//     0.25 LDSM per MMA (was 0.375), halved A-smem traffic per FLOP.
// ============================================================================

#define KDIM 1024
#define MMAIN 8192
#define NMAIN 1024
#define BK 64

// ---- wc gemm: BM=64, BN=128, 3-product (unchanged from R7)
#define WBM 64
#define WBN 128
#define WSTAGES 3
#define WSTAGE_BYTES 49152
#define WSMEM_TOTAL (WSTAGES * WSTAGE_BYTES)   // 144 KB
// ---- main gemm: BM=256, BN=128, 1-product; stage = A 32KB | B 16KB
#define MBM 256
#define MBN 128
#define MSTAGES 3
#define MSTAGE_BYTES 49152
#define MSMEM_TOTAL (MSTAGES * MSTAGE_BYTES)   // 144 KB, 1 CTA/SM

// -------------------- scratch -------------------------------------------------
__device__ __half g_xh[(size_t)MMAIN * KDIM];
__device__ __half g_wph[(size_t)KDIM * KDIM];
__device__ __half g_wpl[(size_t)KDIM * KDIM];
__device__ __half g_wvth[(size_t)KDIM * KDIM];
__device__ __half g_wvtl[(size_t)KDIM * KDIM];
__device__ __half g_wch[(size_t)KDIM * KDIM];
__device__ float g_bcomb[KDIM];

// -------------------- helpers -------------------------------------------------
__device__ __forceinline__ uint32_t sptr(const void* p) {
    return (uint32_t)__cvta_generic_to_shared(p);
}
__device__ __forceinline__ void cp_async16(uint32_t smem, const void* gmem) {
    asm volatile("cp.async.cg.shared.global [%0], [%1], 16;"
                 :: "r"(smem), "l"(gmem) : "memory");
}
__device__ __forceinline__ void cp_commit() {
    asm volatile("cp.async.commit_group;" ::: "memory");
}
template <int N> __device__ __forceinline__ void cp_wait() {
    asm volatile("cp.async.wait_group %0;" :: "n"(N) : "memory");
}
__device__ __forceinline__ void ldmatrix4(uint32_t* r, uint32_t addr) {
    asm volatile("ldmatrix.sync.aligned.m8n8.x4.shared.b16 {%0,%1,%2,%3}, [%4];"
                 : "=r"(r[0]), "=r"(r[1]), "=r"(r[2]), "=r"(r[3]) : "r"(addr));
}
__device__ __forceinline__ void mma16816(float* c, const uint32_t* a,
                                         uint32_t b0, uint32_t b1) {
    asm volatile(
        "mma.sync.aligned.m16n8k16.row.col.f32.f16.f16.f32 "
        "{%0,%1,%2,%3}, {%4,%5,%6,%7}, {%8,%9}, {%0,%1,%2,%3};"
        : "+f"(c[0]), "+f"(c[1]), "+f"(c[2]), "+f"(c[3])
        : "r"(a[0]), "r"(a[1]), "r"(a[2]), "r"(a[3]), "r"(b0), "r"(b1));
}
__device__ __forceinline__ void split2h(float v, __half& hi, __half& lo) {
    hi = __float2half_rn(v);
    lo = __float2half_rn(v - __half2float(hi));
}
__device__ __forceinline__ uint32_t swz(int row, int c) {
    return (uint32_t)(row * 128 + ((c ^ (row & 7)) << 4));
}

// -------------------- prep kernels --------------------------------------------
__global__ __launch_bounds__(256) void bias_combine_kernel(
    const float* __restrict__ Wp, const float* __restrict__ bv,
    const float* __restrict__ bp)
{
    int row = blockIdx.x * 8 + (threadIdx.x >> 5);
    int lane = threadIdx.x & 31;
    float s = 0.f;
    for (int j = lane * 4; j < KDIM; j += 128) {
        float4 w = *(const float4*)(Wp + (size_t)row * KDIM + j);
        float4 b = *(const float4*)(bv + j);
        s += w.x * b.x + w.y * b.y + w.z * b.z + w.w * b.w;
    }
#pragma unroll
    for (int o = 16; o > 0; o >>= 1) s += __shfl_xor_sync(0xffffffff, s, o);
    if (lane == 0) g_bcomb[row] = 2048.0f * s + bp[row];
}

__global__ __launch_bounds__(256) void convert_x_kernel(
    const float* __restrict__ src, __half* __restrict__ dst, int total4)
{
    int idx = blockIdx.x * blockDim.x + threadIdx.x;
    if (idx >= total4) return;
    float4 v = *(const float4*)(src + (size_t)idx * 4);
    *(__half2*)(dst + (size_t)idx * 4) = __floats2half2_rn(v.x, v.y);
    *(__half2*)(dst + (size_t)idx * 4 + 2) = __floats2half2_rn(v.z, v.w);
}

__global__ __launch_bounds__(256) void split_compact_kernel(
    const float* __restrict__ src, __half* __restrict__ hi,
    __half* __restrict__ lo, int total4)
{
    int idx = blockIdx.x * blockDim.x + threadIdx.x;
    if (idx >= total4) return;
    float4 v = *(const float4*)(src + (size_t)idx * 4);
    __half h[4], l[4];
    split2h(v.x, h[0], l[0]);
    split2h(v.y, h[1], l[1]);
    split2h(v.z, h[2], l[2]);
    split2h(v.w, h[3], l[3]);
    __half2 hh0; hh0.x = h[0]; hh0.y = h[1];
    __half2 hh1; hh1.x = h[2]; hh1.y = h[3];
    __half2 ll0; ll0.x = l[0]; ll0.y = l[1];
    __half2 ll1; ll1.x = l[2]; ll1.y = l[3];
    *(__half2*)(hi + (size_t)idx * 4) = hh0;
    *(__half2*)(hi + (size_t)idx * 4 + 2) = hh1;
    *(__half2*)(lo + (size_t)idx * 4) = ll0;
    *(__half2*)(lo + (size_t)idx * 4 + 2) = ll1;
}

__global__ __launch_bounds__(256) void wv_transpose_split_kernel(
    const float* __restrict__ Wv, __half* __restrict__ dhi,
    __half* __restrict__ dlo)
{
    __shared__ float t[32][33];
    int bx = blockIdx.x * 32;
    int by = blockIdx.y * 32;
    int tx = threadIdx.x & 31, ty = threadIdx.x >> 5;
#pragma unroll
    for (int i = 0; i < 32; i += 8)
        t[ty + i][tx] = Wv[(size_t)(by + ty + i) * KDIM + bx + tx];
    __syncthreads();
#pragma unroll
    for (int i = 0; i < 32; i += 8) {
        float v = t[tx][ty + i];
        __half hi, lo;
        split2h(v, hi, lo);
        size_t o = (size_t)(bx + ty + i) * KDIM + by + tx;
        dhi[o] = hi;
        dlo[o] = lo;
    }
}

// -------------------- wc GEMM: 64x128 tiles, 3-product fp16 split -------------
__global__ __launch_bounds__(256, 1) void wc_gemm_kernel(
    const __half* __restrict__ Ahi, const __half* __restrict__ Alo,
    const __half* __restrict__ Bhi, const __half* __restrict__ Blo,
    __half* __restrict__ Ch)
{
    extern __shared__ char smem[];
    const uint32_t sbase = sptr(smem);
    const int tid = threadIdx.x;
    const int wid = tid >> 5, lane = tid & 31;
    const int wm = wid & 1, wn = wid >> 1;
    const int bm = blockIdx.y * WBM, bn = blockIdx.x * WBN;

    float acc[2][4][4];
#pragma unroll
    for (int i = 0; i < 2; i++)
#pragma unroll
        for (int j = 0; j < 4; j++)
#pragma unroll
            for (int q = 0; q < 4; q++) acc[i][j][q] = 0.f;

    auto load_stage = [&](int t, int s) {
        uint32_t st = sbase + s * WSTAGE_BYTES;
        int kcol = t * BK;
#pragma unroll
        for (int i = 0; i < 2; i++) {
            int chunk = tid + i * 256;
            int r = chunk >> 3, c = chunk & 7;
            uint32_t sw = swz(r, c);
            size_t aoff = (size_t)(bm + r) * KDIM + kcol + c * 8;
            cp_async16(st + sw, Ahi + aoff);
            cp_async16(st + 8192 + sw, Alo + aoff);
        }
#pragma unroll
        for (int i = 0; i < 4; i++) {
            int chunk = tid + i * 256;
            int r = chunk >> 3, c = chunk & 7;
            uint32_t sw = swz(r, c);
            size_t boff = (size_t)(bn + r) * KDIM + kcol + c * 8;
            cp_async16(st + 16384 + sw, Bhi + boff);
            cp_async16(st + 32768 + sw, Blo + boff);
        }
    };

    const int NT = KDIM / BK;  // 16
#pragma unroll
    for (int t = 0; t < WSTAGES - 1; t++) { load_stage(t, t); cp_commit(); }

    const int lrow = (lane & 7) + ((lane >> 3) & 1) * 8;
    const int lcol = lane >> 4;

    for (int kt = 0; kt < NT; kt++) {
        cp_wait<WSTAGES - 2>();
        __syncthreads();
        if (kt + WSTAGES - 1 < NT)
            load_stage(kt + WSTAGES - 1, (kt + WSTAGES - 1) % WSTAGES);
        cp_commit();

        uint32_t sah = sbase + (kt % WSTAGES) * WSTAGE_BYTES;
        uint32_t sal = sah + 8192, sbh = sah + 16384, sbl = sah + 32768;

#pragma unroll
        for (int s = 0; s < BK / 16; s++) {
            uint32_t ah[2][4], al[2][4], bh[2][4], bl[2][4];
#pragma unroll
            for (int im = 0; im < 2; im++) {
                uint32_t o = swz(wm * 32 + im * 16 + lrow, s * 2 + lcol);
                ldmatrix4(ah[im], sah + o);
                ldmatrix4(al[im], sal + o);
            }
#pragma unroll
            for (int jn = 0; jn < 2; jn++) {
                uint32_t o = swz(wn * 32 + jn * 16 + lrow, s * 2 + lcol);
                ldmatrix4(bh[jn], sbh + o);
                ldmatrix4(bl[jn], sbl + o);
            }
#pragma unroll
            for (int im = 0; im < 2; im++)
#pragma unroll
                for (int n8 = 0; n8 < 4; n8++) {
                    int jn = n8 >> 1, h = n8 & 1;
                    mma16816(acc[im][n8], ah[im], bh[jn][h], bh[jn][h + 2]);
                    mma16816(acc[im][n8], ah[im], bl[jn][h], bl[jn][h + 2]);
                    mma16816(acc[im][n8], al[im], bh[jn][h], bh[jn][h + 2]);
                }
        }
    }

    const int qr = lane >> 2, qc = lane & 3;
#pragma unroll
    for (int im = 0; im < 2; im++) {
        int m0 = bm + wm * 32 + im * 16 + qr;
#pragma unroll
        for (int n8 = 0; n8 < 4; n8++) {
            int n0 = bn + wn * 32 + n8 * 8 + qc * 2;
            float* c = acc[im][n8];
#pragma unroll
            for (int q = 0; q < 4; q++) {
                int m = m0 + (q >> 1) * 8;
                int n = n0 + (q & 1);
                Ch[(size_t)m * KDIM + n] = __float2half_rn(c[q]);
            }
        }
    }
}

// -------------------- main GEMM: 256x128 CTA, 8 warps of 64x64 ----------------
__global__ __launch_bounds__(256, 1) void main_gemm_kernel(
    const __half* __restrict__ A, const __half* __restrict__ B,
    float* __restrict__ Cout)
{
    extern __shared__ char smem[];
    const uint32_t sbase = sptr(smem);
    const int tid = threadIdx.x;
    const int wid = tid >> 5, lane = tid & 31;
    const int wm = wid & 3;      // 4 M strips of 64
    const int wn = wid >> 2;     // 2 N strips of 64
    const int bm = blockIdx.y * MBM, bn = blockIdx.x * MBN;

    float acc[4][8][4];          // 128 regs
#pragma unroll
    for (int i = 0; i < 4; i++)
#pragma unroll
        for (int j = 0; j < 8; j++)
#pragma unroll
            for (int q = 0; q < 4; q++) acc[i][j][q] = 0.f;

    // stage: A 256x128B = 32KB | B 128x128B = 16KB
    auto load_stage = [&](int t, int s) {
        uint32_t sa = sbase + s * MSTAGE_BYTES;
        uint32_t sb = sa + 32768;
        int kcol = t * BK;
#pragma unroll
        for (int i = 0; i < 8; i++) {       // A: 2048 chunks
            int chunk = tid + i * 256;
            int r = chunk >> 3, c = chunk & 7;
            cp_async16(sa + swz(r, c), A + (size_t)(bm + r) * KDIM + kcol + c * 8);
        }
#pragma unroll
        for (int i = 0; i < 4; i++) {       // B: 1024 chunks
            int chunk = tid + i * 256;
            int r = chunk >> 3, c = chunk & 7;
            cp_async16(sb + swz(r, c), B + (size_t)(bn + r) * KDIM + kcol + c * 8);
        }
    };

    const int NT = KDIM / BK;  // 16
#pragma unroll
    for (int t = 0; t < MSTAGES - 1; t++) { load_stage(t, t); cp_commit(); }

    const int lrow = (lane & 7) + ((lane >> 3) & 1) * 8;
    const int lcol = lane >> 4;

    for (int kt = 0; kt < NT; kt++) {
        cp_wait<MSTAGES - 2>();
        __syncthreads();
        if (kt + MSTAGES - 1 < NT)
            load_stage(kt + MSTAGES - 1, (kt + MSTAGES - 1) % MSTAGES);
        cp_commit();

        uint32_t sa = sbase + (kt % MSTAGES) * MSTAGE_BYTES;
        uint32_t sb = sa + 32768;

#pragma unroll
        for (int s = 0; s < BK / 16; s++) {
            uint32_t af[4][4], bf[4][4];
#pragma unroll
            for (int im = 0; im < 4; im++)
                ldmatrix4(af[im], sa + swz(wm * 64 + im * 16 + lrow,
                                           s * 2 + lcol));
#pragma unroll
            for (int jn = 0; jn < 4; jn++)
                ldmatrix4(bf[jn], sb + swz(wn * 64 + jn * 16 + lrow,
                                           s * 2 + lcol));
#pragma unroll
            for (int im = 0; im < 4; im++)
#pragma unroll
                for (int n8 = 0; n8 < 8; n8++) {
                    int jn = n8 >> 1, h = n8 & 1;
                    mma16816(acc[im][n8], af[im], bf[jn][h], bf[jn][h + 2]);
                }
        }
    }

    const int qr = lane >> 2, qc = lane & 3;
#pragma unroll
    for (int im = 0; im < 4; im++) {
        int m0 = bm + wm * 64 + im * 16 + qr;
#pragma unroll
        for (int n8 = 0; n8 < 8; n8++) {
            int n0 = bn + wn * 64 + n8 * 8 + qc * 2;
            float* c = acc[im][n8];
            float b0 = g_bcomb[n0], b1 = g_bcomb[n0 + 1];
            *(float2*)(Cout + (size_t)m0 * NMAIN + n0) =
                make_float2(2048.f * c[0] + b0, 2048.f * c[1] + b1);
            *(float2*)(Cout + (size_t)(m0 + 8) * NMAIN + n0) =
                make_float2(2048.f * c[2] + b0, 2048.f * c[3] + b1);
        }
    }
}

// -------------------- host ------------------------------------------------------
extern "C" void kernel_launch(void* const* d_in, const int* in_sizes, int n_in,
                              void* d_out, int out_size)
{
    // metadata order: x, Wq, bq, Wk, bk, Wv, bv, Wp, bp
    const float* x  = (const float*)d_in[0];
    const float* Wv = (const float*)d_in[5];
    const float* bv = (const float*)d_in[6];
    const float* Wp = (const float*)d_in[7];
    const float* bp = (const float*)d_in[8];
    float* out = (float*)d_out;

    __half *xh, *wph, *wpl, *wvth, *wvtl, *wch;
    cudaGetSymbolAddress((void**)&xh, g_xh);
    cudaGetSymbolAddress((void**)&wph, g_wph);
    cudaGetSymbolAddress((void**)&wpl, g_wpl);
    cudaGetSymbolAddress((void**)&wvth, g_wvth);
    cudaGetSymbolAddress((void**)&wvtl, g_wvtl);
    cudaGetSymbolAddress((void**)&wch, g_wch);

    cudaFuncSetAttribute(wc_gemm_kernel,
                         cudaFuncAttributeMaxDynamicSharedMemorySize, WSMEM_TOTAL);
    cudaFuncSetAttribute(main_gemm_kernel,
                         cudaFuncAttributeMaxDynamicSharedMemorySize, MSMEM_TOTAL);

    bias_combine_kernel<<<128, 256>>>(Wp, bv, bp);
    convert_x_kernel<<<(MMAIN * KDIM / 4 + 255) / 256, 256>>>(x, xh,
                                                              MMAIN * KDIM / 4);
    split_compact_kernel<<<(KDIM * KDIM / 4 + 255) / 256, 256>>>(Wp, wph, wpl,
                                                                 KDIM * KDIM / 4);
    wv_transpose_split_kernel<<<dim3(32, 32), 256>>>(Wv, wvth, wvtl);

    wc_gemm_kernel<<<dim3(8, 16), 256, WSMEM_TOTAL>>>(wph, wpl, wvth, wvtl, wch);
    main_gemm_kernel<<<dim3(8, 32), 256, MSMEM_TOTAL>>>(xh, wch, out);
}

// round 9
// speedup vs baseline: 1.0191x; 1.0191x over previous
#include <cuda_runtime.h>
#include <cuda_fp16.h>
#include <cstdint>

// ============================================================================
// Collapse (verified): out = 2048 * x @ (Wp@Wv)^T + (2048*Wp@bv + bp)
// fp16 HMMA path (rel_err 2.9e-4).
// R9: main GEMM = CTA 128x128 with FOUR warps (2x2 of 64x64 warp tiles),
//     96KB smem -> 2 CTAs/SM. Combines R8's 0.25 LDSM/MMA ratio with R7's
//     dual-CTA latency hiding (R8 showed 1 CTA/SM loses ~2.5%).
// ============================================================================

#define KDIM 1024
#define MMAIN 8192
#define NMAIN 1024
#define BK 64

// ---- wc gemm: BM=64, BN=128, 3-product (frozen since R7)
#define WBM 64
#define WBN 128
#define WSTAGES 3
#define WSTAGE_BYTES 49152
#define WSMEM_TOTAL (WSTAGES * WSTAGE_BYTES)   // 144 KB
// ---- main gemm: BM=BN=128, 1-product, 128 threads; stage = A|B = 32KB
#define MBM 128
#define MBN 128
#define MSTAGES 3
#define MSTAGE_BYTES 32768
#define MSMEM_TOTAL (MSTAGES * MSTAGE_BYTES)   // 96 KB -> 2 CTAs/SM

// -------------------- scratch -------------------------------------------------
__device__ __half g_xh[(size_t)MMAIN * KDIM];
__device__ __half g_wph[(size_t)KDIM * KDIM];
__device__ __half g_wpl[(size_t)KDIM * KDIM];
__device__ __half g_wvth[(size_t)KDIM * KDIM];
__device__ __half g_wvtl[(size_t)KDIM * KDIM];
__device__ __half g_wch[(size_t)KDIM * KDIM];
__device__ float g_bcomb[KDIM];

// -------------------- helpers -------------------------------------------------
__device__ __forceinline__ uint32_t sptr(const void* p) {
    return (uint32_t)__cvta_generic_to_shared(p);
}
__device__ __forceinline__ void cp_async16(uint32_t smem, const void* gmem) {
    asm volatile("cp.async.cg.shared.global [%0], [%1], 16;"
                 :: "r"(smem), "l"(gmem) : "memory");
}
__device__ __forceinline__ void cp_commit() {
    asm volatile("cp.async.commit_group;" ::: "memory");
}
template <int N> __device__ __forceinline__ void cp_wait() {
    asm volatile("cp.async.wait_group %0;" :: "n"(N) : "memory");
}
__device__ __forceinline__ void ldmatrix4(uint32_t* r, uint32_t addr) {
    asm volatile("ldmatrix.sync.aligned.m8n8.x4.shared.b16 {%0,%1,%2,%3}, [%4];"
                 : "=r"(r[0]), "=r"(r[1]), "=r"(r[2]), "=r"(r[3]) : "r"(addr));
}
__device__ __forceinline__ void mma16816(float* c, const uint32_t* a,
                                         uint32_t b0, uint32_t b1) {
    asm volatile(
        "mma.sync.aligned.m16n8k16.row.col.f32.f16.f16.f32 "
        "{%0,%1,%2,%3}, {%4,%5,%6,%7}, {%8,%9}, {%0,%1,%2,%3};"
        : "+f"(c[0]), "+f"(c[1]), "+f"(c[2]), "+f"(c[3])
        : "r"(a[0]), "r"(a[1]), "r"(a[2]), "r"(a[3]), "r"(b0), "r"(b1));
}
__device__ __forceinline__ void split2h(float v, __half& hi, __half& lo) {
    hi = __float2half_rn(v);
    lo = __float2half_rn(v - __half2float(hi));
}
__device__ __forceinline__ uint32_t swz(int row, int c) {
    return (uint32_t)(row * 128 + ((c ^ (row & 7)) << 4));
}

// -------------------- prep kernels --------------------------------------------
__global__ __launch_bounds__(256) void bias_combine_kernel(
    const float* __restrict__ Wp, const float* __restrict__ bv,
    const float* __restrict__ bp)
{
    int row = blockIdx.x * 8 + (threadIdx.x >> 5);
    int lane = threadIdx.x & 31;
    float s = 0.f;
    for (int j = lane * 4; j < KDIM; j += 128) {
        float4 w = *(const float4*)(Wp + (size_t)row * KDIM + j);
        float4 b = *(const float4*)(bv + j);
        s += w.x * b.x + w.y * b.y + w.z * b.z + w.w * b.w;
    }
#pragma unroll
    for (int o = 16; o > 0; o >>= 1) s += __shfl_xor_sync(0xffffffff, s, o);
    if (lane == 0) g_bcomb[row] = 2048.0f * s + bp[row];
}

__global__ __launch_bounds__(256) void convert_x_kernel(
    const float* __restrict__ src, __half* __restrict__ dst, int total4)
{
    int idx = blockIdx.x * blockDim.x + threadIdx.x;
    if (idx >= total4) return;
    float4 v = *(const float4*)(src + (size_t)idx * 4);
    *(__half2*)(dst + (size_t)idx * 4) = __floats2half2_rn(v.x, v.y);
    *(__half2*)(dst + (size_t)idx * 4 + 2) = __floats2half2_rn(v.z, v.w);
}

__global__ __launch_bounds__(256) void split_compact_kernel(
    const float* __restrict__ src, __half* __restrict__ hi,
    __half* __restrict__ lo, int total4)
{
    int idx = blockIdx.x * blockDim.x + threadIdx.x;
    if (idx >= total4) return;
    float4 v = *(const float4*)(src + (size_t)idx * 4);
    __half h[4], l[4];
    split2h(v.x, h[0], l[0]);
    split2h(v.y, h[1], l[1]);
    split2h(v.z, h[2], l[2]);
    split2h(v.w, h[3], l[3]);
    __half2 hh0; hh0.x = h[0]; hh0.y = h[1];
    __half2 hh1; hh1.x = h[2]; hh1.y = h[3];
    __half2 ll0; ll0.x = l[0]; ll0.y = l[1];
    __half2 ll1; ll1.x = l[2]; ll1.y = l[3];
    *(__half2*)(hi + (size_t)idx * 4) = hh0;
    *(__half2*)(hi + (size_t)idx * 4 + 2) = hh1;
    *(__half2*)(lo + (size_t)idx * 4) = ll0;
    *(__half2*)(lo + (size_t)idx * 4 + 2) = ll1;
}

__global__ __launch_bounds__(256) void wv_transpose_split_kernel(
    const float* __restrict__ Wv, __half* __restrict__ dhi,
    __half* __restrict__ dlo)
{
    __shared__ float t[32][33];
    int bx = blockIdx.x * 32;
    int by = blockIdx.y * 32;
    int tx = threadIdx.x & 31, ty = threadIdx.x >> 5;
#pragma unroll
    for (int i = 0; i < 32; i += 8)
        t[ty + i][tx] = Wv[(size_t)(by + ty + i) * KDIM + bx + tx];
    __syncthreads();
#pragma unroll
    for (int i = 0; i < 32; i += 8) {
        float v = t[tx][ty + i];
        __half hi, lo;
        split2h(v, hi, lo);
        size_t o = (size_t)(bx + ty + i) * KDIM + by + tx;
        dhi[o] = hi;
        dlo[o] = lo;
    }
}

// -------------------- wc GEMM: 64x128 tiles, 3-product fp16 split -------------
__global__ __launch_bounds__(256, 1) void wc_gemm_kernel(
    const __half* __restrict__ Ahi, const __half* __restrict__ Alo,
    const __half* __restrict__ Bhi, const __half* __restrict__ Blo,
    __half* __restrict__ Ch)
{
    extern __shared__ char smem[];
    const uint32_t sbase = sptr(smem);
    const int tid = threadIdx.x;
    const int wid = tid >> 5, lane = tid & 31;
    const int wm = wid & 1, wn = wid >> 1;
    const int bm = blockIdx.y * WBM, bn = blockIdx.x * WBN;

    float acc[2][4][4];
#pragma unroll
    for (int i = 0; i < 2; i++)
#pragma unroll
        for (int j = 0; j < 4; j++)
#pragma unroll
            for (int q = 0; q < 4; q++) acc[i][j][q] = 0.f;

    auto load_stage = [&](int t, int s) {
        uint32_t st = sbase + s * WSTAGE_BYTES;
        int kcol = t * BK;
#pragma unroll
        for (int i = 0; i < 2; i++) {
            int chunk = tid + i * 256;
            int r = chunk >> 3, c = chunk & 7;
            uint32_t sw = swz(r, c);
            size_t aoff = (size_t)(bm + r) * KDIM + kcol + c * 8;
            cp_async16(st + sw, Ahi + aoff);
            cp_async16(st + 8192 + sw, Alo + aoff);
        }
#pragma unroll
        for (int i = 0; i < 4; i++) {
            int chunk = tid + i * 256;
            int r = chunk >> 3, c = chunk & 7;
            uint32_t sw = swz(r, c);
            size_t boff = (size_t)(bn + r) * KDIM + kcol + c * 8;
            cp_async16(st + 16384 + sw, Bhi + boff);
            cp_async16(st + 32768 + sw, Blo + boff);
        }
    };

    const int NT = KDIM / BK;  // 16
#pragma unroll
    for (int t = 0; t < WSTAGES - 1; t++) { load_stage(t, t); cp_commit(); }

    const int lrow = (lane & 7) + ((lane >> 3) & 1) * 8;
    const int lcol = lane >> 4;

    for (int kt = 0; kt < NT; kt++) {
        cp_wait<WSTAGES - 2>();
        __syncthreads();
        if (kt + WSTAGES - 1 < NT)
            load_stage(kt + WSTAGES - 1, (kt + WSTAGES - 1) % WSTAGES);
        cp_commit();

        uint32_t sah = sbase + (kt % WSTAGES) * WSTAGE_BYTES;
        uint32_t sal = sah + 8192, sbh = sah + 16384, sbl = sah + 32768;

#pragma unroll
        for (int s = 0; s < BK / 16; s++) {
            uint32_t ah[2][4], al[2][4], bh[2][4], bl[2][4];
#pragma unroll
            for (int im = 0; im < 2; im++) {
                uint32_t o = swz(wm * 32 + im * 16 + lrow, s * 2 + lcol);
                ldmatrix4(ah[im], sah + o);
                ldmatrix4(al[im], sal + o);
            }
#pragma unroll
            for (int jn = 0; jn < 2; jn++) {
                uint32_t o = swz(wn * 32 + jn * 16 + lrow, s * 2 + lcol);
                ldmatrix4(bh[jn], sbh + o);
                ldmatrix4(bl[jn], sbl + o);
            }
#pragma unroll
            for (int im = 0; im < 2; im++)
#pragma unroll
                for (int n8 = 0; n8 < 4; n8++) {
                    int jn = n8 >> 1, h = n8 & 1;
                    mma16816(acc[im][n8], ah[im], bh[jn][h], bh[jn][h + 2]);
                    mma16816(acc[im][n8], ah[im], bl[jn][h], bl[jn][h + 2]);
                    mma16816(acc[im][n8], al[im], bh[jn][h], bh[jn][h + 2]);
                }
        }
    }

    const int qr = lane >> 2, qc = lane & 3;
#pragma unroll
    for (int im = 0; im < 2; im++) {
        int m0 = bm + wm * 32 + im * 16 + qr;
#pragma unroll
        for (int n8 = 0; n8 < 4; n8++) {
            int n0 = bn + wn * 32 + n8 * 8 + qc * 2;
            float* c = acc[im][n8];
#pragma unroll
            for (int q = 0; q < 4; q++) {
                int m = m0 + (q >> 1) * 8;
                int n = n0 + (q & 1);
                Ch[(size_t)m * KDIM + n] = __float2half_rn(c[q]);
            }
        }
    }
}

// -------------------- main GEMM: 128x128 CTA, 4 warps of 64x64, 2 CTA/SM ------
__global__ __launch_bounds__(128, 2) void main_gemm_kernel(
    const __half* __restrict__ A, const __half* __restrict__ B,
    float* __restrict__ Cout)
{
    extern __shared__ char smem[];
    const uint32_t sbase = sptr(smem);
    const int tid = threadIdx.x;
    const int wid = tid >> 5, lane = tid & 31;
    const int wm = wid & 1;      // 2 M strips of 64
    const int wn = wid >> 1;     // 2 N strips of 64
    const int bm = blockIdx.y * MBM, bn = blockIdx.x * MBN;

    float acc[4][8][4];          // 128 regs
#pragma unroll
    for (int i = 0; i < 4; i++)
#pragma unroll
        for (int j = 0; j < 8; j++)
#pragma unroll
            for (int q = 0; q < 4; q++) acc[i][j][q] = 0.f;

    // stage: A 128x128B = 16KB | B 128x128B = 16KB ; 128 threads -> 8+8 iters
    auto load_stage = [&](int t, int s) {
        uint32_t sa = sbase + s * MSTAGE_BYTES;
        uint32_t sb = sa + 16384;
        int kcol = t * BK;
#pragma unroll
        for (int i = 0; i < 8; i++) {
            int chunk = tid + i * 128;         // 0..1023
            int r = chunk >> 3, c = chunk & 7;
            uint32_t sw = swz(r, c);
            cp_async16(sa + sw, A + (size_t)(bm + r) * KDIM + kcol + c * 8);
            cp_async16(sb + sw, B + (size_t)(bn + r) * KDIM + kcol + c * 8);
        }
    };

    const int NT = KDIM / BK;  // 16
#pragma unroll
    for (int t = 0; t < MSTAGES - 1; t++) { load_stage(t, t); cp_commit(); }

    const int lrow = (lane & 7) + ((lane >> 3) & 1) * 8;
    const int lcol = lane >> 4;

    for (int kt = 0; kt < NT; kt++) {
        cp_wait<MSTAGES - 2>();
        __syncthreads();
        if (kt + MSTAGES - 1 < NT)
            load_stage(kt + MSTAGES - 1, (kt + MSTAGES - 1) % MSTAGES);
        cp_commit();

        uint32_t sa = sbase + (kt % MSTAGES) * MSTAGE_BYTES;
        uint32_t sb = sa + 16384;

#pragma unroll
        for (int s = 0; s < BK / 16; s++) {
            uint32_t af[4][4], bf[4][4];
#pragma unroll
            for (int im = 0; im < 4; im++)
                ldmatrix4(af[im], sa + swz(wm * 64 + im * 16 + lrow,
                                           s * 2 + lcol));
#pragma unroll
            for (int jn = 0; jn < 4; jn++)
                ldmatrix4(bf[jn], sb + swz(wn * 64 + jn * 16 + lrow,
                                           s * 2 + lcol));
#pragma unroll
            for (int im = 0; im < 4; im++)
#pragma unroll
                for (int n8 = 0; n8 < 8; n8++) {
                    int jn = n8 >> 1, h = n8 & 1;
                    mma16816(acc[im][n8], af[im], bf[jn][h], bf[jn][h + 2]);
                }
        }
    }

    const int qr = lane >> 2, qc = lane & 3;
#pragma unroll
    for (int im = 0; im < 4; im++) {
        int m0 = bm + wm * 64 + im * 16 + qr;
#pragma unroll
        for (int n8 = 0; n8 < 8; n8++) {
            int n0 = bn + wn * 64 + n8 * 8 + qc * 2;
            float* c = acc[im][n8];
            float b0 = g_bcomb[n0], b1 = g_bcomb[n0 + 1];
            *(float2*)(Cout + (size_t)m0 * NMAIN + n0) =
                make_float2(2048.f * c[0] + b0, 2048.f * c[1] + b1);
            *(float2*)(Cout + (size_t)(m0 + 8) * NMAIN + n0) =
                make_float2(2048.f * c[2] + b0, 2048.f * c[3] + b1);
        }
    }
}

// -------------------- host ------------------------------------------------------
extern "C" void kernel_launch(void* const* d_in, const int* in_sizes, int n_in,
                              void* d_out, int out_size)
{
    // metadata order: x, Wq, bq, Wk, bk, Wv, bv, Wp, bp
    const float* x  = (const float*)d_in[0];
    const float* Wv = (const float*)d_in[5];
    const float* bv = (const float*)d_in[6];
    const float* Wp = (const float*)d_in[7];
    const float* bp = (const float*)d_in[8];
    float* out = (float*)d_out;

    __half *xh, *wph, *wpl, *wvth, *wvtl, *wch;
    cudaGetSymbolAddress((void**)&xh, g_xh);
    cudaGetSymbolAddress((void**)&wph, g_wph);
    cudaGetSymbolAddress((void**)&wpl, g_wpl);
    cudaGetSymbolAddress((void**)&wvth, g_wvth);
    cudaGetSymbolAddress((void**)&wvtl, g_wvtl);
    cudaGetSymbolAddress((void**)&wch, g_wch);

    cudaFuncSetAttribute(wc_gemm_kernel,
                         cudaFuncAttributeMaxDynamicSharedMemorySize, WSMEM_TOTAL);
    cudaFuncSetAttribute(main_gemm_kernel,
                         cudaFuncAttributeMaxDynamicSharedMemorySize, MSMEM_TOTAL);

    bias_combine_kernel<<<128, 256>>>(Wp, bv, bp);
    convert_x_kernel<<<(MMAIN * KDIM / 4 + 255) / 256, 256>>>(x, xh,
                                                              MMAIN * KDIM / 4);
    split_compact_kernel<<<(KDIM * KDIM / 4 + 255) / 256, 256>>>(Wp, wph, wpl,
                                                                 KDIM * KDIM / 4);
    wv_transpose_split_kernel<<<dim3(32, 32), 256>>>(Wv, wvth, wvtl);

    wc_gemm_kernel<<<dim3(8, 16), 256, WSMEM_TOTAL>>>(wph, wpl, wvth, wvtl, wch);
    main_gemm_kernel<<<dim3(8, 64), 128, MSMEM_TOTAL>>>(xh, wch, out);
}

// round 10
// speedup vs baseline: 1.0990x; 1.0784x over previous
#include <cuda_runtime.h>
#include <cuda_fp16.h>
#include <cstdint>

// ============================================================================
// Collapse (verified): out = 2048 * x @ (Wp@Wv)^T + (2048*Wp@bv + bp)
// fp16 HMMA path (rel_err 2.9e-4).
// R10: kill the serial prep chain.
//  - one fused prep kernel: bias + split(Wp) + transpose-split(Wv), block-
//    partitioned so the three tasks run concurrently (~28MB, bw-bound).
//  - convert_x folded INTO wc_gemm's k-loop (LDG before MMA block, cvt+STG
//    after) -> overlaps with tensor work on wc's idle LSU/DRAM pipes.
//  Launches: 6 -> 3. Main GEMM frozen (R9: 128x128 CTA, 4 warps, 2 CTA/SM).
// ============================================================================

#define KDIM 1024
#define MMAIN 8192
#define NMAIN 1024
#define BK 64

// ---- wc gemm: BM=64, BN=128, 3-product
#define WBM 64
#define WBN 128
#define WSTAGES 3
#define WSTAGE_BYTES 49152
#define WSMEM_TOTAL (WSTAGES * WSTAGE_BYTES)   // 144 KB
// ---- main gemm: BM=BN=128, 1-product, 128 threads; stage = A|B = 32KB
#define MBM 128
#define MBN 128
#define MSTAGES 3
#define MSTAGE_BYTES 32768
#define MSMEM_TOTAL (MSTAGES * MSTAGE_BYTES)   // 96 KB -> 2 CTAs/SM

// -------------------- scratch -------------------------------------------------
__device__ __half g_xh[(size_t)MMAIN * KDIM];
__device__ __half g_wph[(size_t)KDIM * KDIM];
__device__ __half g_wpl[(size_t)KDIM * KDIM];
__device__ __half g_wvth[(size_t)KDIM * KDIM];
__device__ __half g_wvtl[(size_t)KDIM * KDIM];
__device__ __half g_wch[(size_t)KDIM * KDIM];
__device__ float g_bcomb[KDIM];

// -------------------- helpers -------------------------------------------------
__device__ __forceinline__ uint32_t sptr(const void* p) {
    return (uint32_t)__cvta_generic_to_shared(p);
}
__device__ __forceinline__ void cp_async16(uint32_t smem, const void* gmem) {
    asm volatile("cp.async.cg.shared.global [%0], [%1], 16;"
                 :: "r"(smem), "l"(gmem) : "memory");
}
__device__ __forceinline__ void cp_commit() {
    asm volatile("cp.async.commit_group;" ::: "memory");
}
template <int N> __device__ __forceinline__ void cp_wait() {
    asm volatile("cp.async.wait_group %0;" :: "n"(N) : "memory");
}
__device__ __forceinline__ void ldmatrix4(uint32_t* r, uint32_t addr) {
    asm volatile("ldmatrix.sync.aligned.m8n8.x4.shared.b16 {%0,%1,%2,%3}, [%4];"
                 : "=r"(r[0]), "=r"(r[1]), "=r"(r[2]), "=r"(r[3]) : "r"(addr));
}
__device__ __forceinline__ void mma16816(float* c, const uint32_t* a,
                                         uint32_t b0, uint32_t b1) {
    asm volatile(
        "mma.sync.aligned.m16n8k16.row.col.f32.f16.f16.f32 "
        "{%0,%1,%2,%3}, {%4,%5,%6,%7}, {%8,%9}, {%0,%1,%2,%3};"
        : "+f"(c[0]), "+f"(c[1]), "+f"(c[2]), "+f"(c[3])
        : "r"(a[0]), "r"(a[1]), "r"(a[2]), "r"(a[3]), "r"(b0), "r"(b1));
}
__device__ __forceinline__ void split2h(float v, __half& hi, __half& lo) {
    hi = __float2half_rn(v);
    lo = __float2half_rn(v - __half2float(hi));
}
__device__ __forceinline__ uint32_t swz(int row, int c) {
    return (uint32_t)(row * 128 + ((c ^ (row & 7)) << 4));
}

// -------------------- fused prep kernel ----------------------------------------
// grid = 1280 blocks x 256 threads, partitioned:
//   [0, 1024)     : Wv transpose+split, one 32x32 tile per block
//   [1024, 1152)  : Wp hi/lo split, 2048 float4 per block
//   [1152, 1280)  : bias_combine, 8 rows per block (warp per row)
__global__ __launch_bounds__(256) void prep_kernel(
    const float* __restrict__ Wv, const float* __restrict__ Wp,
    const float* __restrict__ bv, const float* __restrict__ bp,
    __half* __restrict__ wvth, __half* __restrict__ wvtl,
    __half* __restrict__ wph, __half* __restrict__ wpl)
{
    __shared__ float t[32][33];
    int b = blockIdx.x;
    int tid = threadIdx.x;

    if (b < 1024) {
        // Wv [K,N] -> Wv^T fp16 hi/lo [N,K], tile (bx, by)
        int bx = (b & 31) * 32;    // n base
        int by = (b >> 5) * 32;    // k base
        int tx = tid & 31, ty = tid >> 5;
#pragma unroll
        for (int i = 0; i < 32; i += 8)
            t[ty + i][tx] = Wv[(size_t)(by + ty + i) * KDIM + bx + tx];
        __syncthreads();
#pragma unroll
        for (int i = 0; i < 32; i += 8) {
            float v = t[tx][ty + i];
            __half hi, lo;
            split2h(v, hi, lo);
            size_t o = (size_t)(bx + ty + i) * KDIM + by + tx;
            wvth[o] = hi;
            wvtl[o] = lo;
        }
    } else if (b < 1152) {
        // Wp split: blocks handle 262144 float4 total
        int blk = b - 1024;
#pragma unroll
        for (int i = 0; i < 8; i++) {
            size_t idx = (size_t)blk * 2048 + i * 256 + tid;
            float4 v = *(const float4*)(Wp + idx * 4);
            __half h[4], l[4];
            split2h(v.x, h[0], l[0]);
            split2h(v.y, h[1], l[1]);
            split2h(v.z, h[2], l[2]);
            split2h(v.w, h[3], l[3]);
            __half2 hh0; hh0.x = h[0]; hh0.y = h[1];
            __half2 hh1; hh1.x = h[2]; hh1.y = h[3];
            __half2 ll0; ll0.x = l[0]; ll0.y = l[1];
            __half2 ll1; ll1.x = l[2]; ll1.y = l[3];
            *(__half2*)(wph + idx * 4) = hh0;
            *(__half2*)(wph + idx * 4 + 2) = hh1;
            *(__half2*)(wpl + idx * 4) = ll0;
            *(__half2*)(wpl + idx * 4 + 2) = ll1;
        }
    } else {
        // bias: row per warp
        int row = (b - 1152) * 8 + (tid >> 5);
        int lane = tid & 31;
        float s = 0.f;
        for (int j = lane * 4; j < KDIM; j += 128) {
            float4 w = *(const float4*)(Wp + (size_t)row * KDIM + j);
            float4 bb = *(const float4*)(bv + j);
            s += w.x * bb.x + w.y * bb.y + w.z * bb.z + w.w * bb.w;
        }
#pragma unroll
        for (int o = 16; o > 0; o >>= 1) s += __shfl_xor_sync(0xffffffff, s, o);
        if (lane == 0) g_bcomb[row] = 2048.0f * s + bp[row];
    }
}

// -------------------- wc GEMM (+ interleaved x conversion) --------------------
// Wc = Wp @ Wv (3-product fp16 split). Additionally each CTA converts a
// 65536-float slice of x to fp16, 4 float4 per thread per k-iter: LDGs issued
// before the MMA block (latency hidden under 48 MMAs), cvt+STG after.
__global__ __launch_bounds__(256, 1) void wc_gemm_kernel(
    const __half* __restrict__ Ahi, const __half* __restrict__ Alo,
    const __half* __restrict__ Bhi, const __half* __restrict__ Blo,
    __half* __restrict__ Ch,
    const float* __restrict__ Xsrc, __half* __restrict__ Xdst)
{
    extern __shared__ char smem[];
    const uint32_t sbase = sptr(smem);
    const int tid = threadIdx.x;
    const int wid = tid >> 5, lane = tid & 31;
    const int wm = wid & 1, wn = wid >> 1;
    const int bm = blockIdx.y * WBM, bn = blockIdx.x * WBN;
    const int cta = blockIdx.y * gridDim.x + blockIdx.x;   // 0..127
    const size_t xbase = (size_t)cta * 16384;              // float4 units

    float acc[2][4][4];
#pragma unroll
    for (int i = 0; i < 2; i++)
#pragma unroll
        for (int j = 0; j < 4; j++)
#pragma unroll
            for (int q = 0; q < 4; q++) acc[i][j][q] = 0.f;

    auto load_stage = [&](int t, int s) {
        uint32_t st = sbase + s * WSTAGE_BYTES;
        int kcol = t * BK;
#pragma unroll
        for (int i = 0; i < 2; i++) {
            int chunk = tid + i * 256;
            int r = chunk >> 3, c = chunk & 7;
            uint32_t sw = swz(r, c);
            size_t aoff = (size_t)(bm + r) * KDIM + kcol + c * 8;
            cp_async16(st + sw, Ahi + aoff);
            cp_async16(st + 8192 + sw, Alo + aoff);
        }
#pragma unroll
        for (int i = 0; i < 4; i++) {
            int chunk = tid + i * 256;
            int r = chunk >> 3, c = chunk & 7;
            uint32_t sw = swz(r, c);
            size_t boff = (size_t)(bn + r) * KDIM + kcol + c * 8;
            cp_async16(st + 16384 + sw, Bhi + boff);
            cp_async16(st + 32768 + sw, Blo + boff);
        }
    };

    const int NT = KDIM / BK;  // 16
#pragma unroll
    for (int t = 0; t < WSTAGES - 1; t++) { load_stage(t, t); cp_commit(); }

    const int lrow = (lane & 7) + ((lane >> 3) & 1) * 8;
    const int lcol = lane >> 4;

    for (int kt = 0; kt < NT; kt++) {
        cp_wait<WSTAGES - 2>();
        __syncthreads();
        if (kt + WSTAGES - 1 < NT)
            load_stage(kt + WSTAGES - 1, (kt + WSTAGES - 1) % WSTAGES);
        cp_commit();

        // --- x conversion: issue LDGs now, latency hides under the MMAs ---
        float4 xv[4];
        size_t xo = xbase + (size_t)kt * 1024 + tid;
#pragma unroll
        for (int i = 0; i < 4; i++)
            xv[i] = __ldg((const float4*)Xsrc + xo + i * 256);

        uint32_t sah = sbase + (kt % WSTAGES) * WSTAGE_BYTES;
        uint32_t sal = sah + 8192, sbh = sah + 16384, sbl = sah + 32768;

#pragma unroll
        for (int s = 0; s < BK / 16; s++) {
            uint32_t ah[2][4], al[2][4], bh[2][4], bl[2][4];
#pragma unroll
            for (int im = 0; im < 2; im++) {
                uint32_t o = swz(wm * 32 + im * 16 + lrow, s * 2 + lcol);
                ldmatrix4(ah[im], sah + o);
                ldmatrix4(al[im], sal + o);
            }
#pragma unroll
            for (int jn = 0; jn < 2; jn++) {
                uint32_t o = swz(wn * 32 + jn * 16 + lrow, s * 2 + lcol);
                ldmatrix4(bh[jn], sbh + o);
                ldmatrix4(bl[jn], sbl + o);
            }
#pragma unroll
            for (int im = 0; im < 2; im++)
#pragma unroll
                for (int n8 = 0; n8 < 4; n8++) {
                    int jn = n8 >> 1, h = n8 & 1;
                    mma16816(acc[im][n8], ah[im], bh[jn][h], bh[jn][h + 2]);
                    mma16816(acc[im][n8], ah[im], bl[jn][h], bl[jn][h + 2]);
                    mma16816(acc[im][n8], al[im], bh[jn][h], bh[jn][h + 2]);
                }
        }

        // --- x conversion: convert + store ---
#pragma unroll
        for (int i = 0; i < 4; i++) {
            __half2 h0 = __floats2half2_rn(xv[i].x, xv[i].y);
            __half2 h1 = __floats2half2_rn(xv[i].z, xv[i].w);
            uint2 pk;
            pk.x = *reinterpret_cast<uint32_t*>(&h0);
            pk.y = *reinterpret_cast<uint32_t*>(&h1);
            *reinterpret_cast<uint2*>(Xdst + (xo + i * 256) * 4) = pk;
        }
    }

    const int qr = lane >> 2, qc = lane & 3;
#pragma unroll
    for (int im = 0; im < 2; im++) {
        int m0 = bm + wm * 32 + im * 16 + qr;
#pragma unroll
        for (int n8 = 0; n8 < 4; n8++) {
            int n0 = bn + wn * 32 + n8 * 8 + qc * 2;
            float* c = acc[im][n8];
#pragma unroll
            for (int q = 0; q < 4; q++) {
                int m = m0 + (q >> 1) * 8;
                int n = n0 + (q & 1);
                Ch[(size_t)m * KDIM + n] = __float2half_rn(c[q]);
            }
        }
    }
}

// -------------------- main GEMM: 128x128 CTA, 4 warps of 64x64, 2 CTA/SM ------
__global__ __launch_bounds__(128, 2) void main_gemm_kernel(
    const __half* __restrict__ A, const __half* __restrict__ B,
    float* __restrict__ Cout)
{
    extern __shared__ char smem[];
    const uint32_t sbase = sptr(smem);
    const int tid = threadIdx.x;
    const int wid = tid >> 5, lane = tid & 31;
    const int wm = wid & 1;
    const int wn = wid >> 1;
    const int bm = blockIdx.y * MBM, bn = blockIdx.x * MBN;

    float acc[4][8][4];
#pragma unroll
    for (int i = 0; i < 4; i++)
#pragma unroll
        for (int j = 0; j < 8; j++)
#pragma unroll
            for (int q = 0; q < 4; q++) acc[i][j][q] = 0.f;

    auto load_stage = [&](int t, int s) {
        uint32_t sa = sbase + s * MSTAGE_BYTES;
        uint32_t sb = sa + 16384;
        int kcol = t * BK;
#pragma unroll
        for (int i = 0; i < 8; i++) {
            int chunk = tid + i * 128;
            int r = chunk >> 3, c = chunk & 7;
            uint32_t sw = swz(r, c);
            cp_async16(sa + sw, A + (size_t)(bm + r) * KDIM + kcol + c * 8);
            cp_async16(sb + sw, B + (size_t)(bn + r) * KDIM + kcol + c * 8);
        }
    };

    const int NT = KDIM / BK;  // 16
#pragma unroll
    for (int t = 0; t < MSTAGES - 1; t++) { load_stage(t, t); cp_commit(); }

    const int lrow = (lane & 7) + ((lane >> 3) & 1) * 8;
    const int lcol = lane >> 4;

    for (int kt = 0; kt < NT; kt++) {
        cp_wait<MSTAGES - 2>();
        __syncthreads();
        if (kt + MSTAGES - 1 < NT)
            load_stage(kt + MSTAGES - 1, (kt + MSTAGES - 1) % MSTAGES);
        cp_commit();

        uint32_t sa = sbase + (kt % MSTAGES) * MSTAGE_BYTES;
        uint32_t sb = sa + 16384;

#pragma unroll
        for (int s = 0; s < BK / 16; s++) {
            uint32_t af[4][4], bf[4][4];
#pragma unroll
            for (int im = 0; im < 4; im++)
                ldmatrix4(af[im], sa + swz(wm * 64 + im * 16 + lrow,
                                           s * 2 + lcol));
#pragma unroll
            for (int jn = 0; jn < 4; jn++)
                ldmatrix4(bf[jn], sb + swz(wn * 64 + jn * 16 + lrow,
                                           s * 2 + lcol));
#pragma unroll
            for (int im = 0; im < 4; im++)
#pragma unroll
                for (int n8 = 0; n8 < 8; n8++) {
                    int jn = n8 >> 1, h = n8 & 1;
                    mma16816(acc[im][n8], af[im], bf[jn][h], bf[jn][h + 2]);
                }
        }
    }

    const int qr = lane >> 2, qc = lane & 3;
#pragma unroll
    for (int im = 0; im < 4; im++) {
        int m0 = bm + wm * 64 + im * 16 + qr;
#pragma unroll
        for (int n8 = 0; n8 < 8; n8++) {
            int n0 = bn + wn * 64 + n8 * 8 + qc * 2;
            float* c = acc[im][n8];
            float b0 = g_bcomb[n0], b1 = g_bcomb[n0 + 1];
            *(float2*)(Cout + (size_t)m0 * NMAIN + n0) =
                make_float2(2048.f * c[0] + b0, 2048.f * c[1] + b1);
            *(float2*)(Cout + (size_t)(m0 + 8) * NMAIN + n0) =
                make_float2(2048.f * c[2] + b0, 2048.f * c[3] + b1);
        }
    }
}

// -------------------- host ------------------------------------------------------
extern "C" void kernel_launch(void* const* d_in, const int* in_sizes, int n_in,
                              void* d_out, int out_size)
{
    // metadata order: x, Wq, bq, Wk, bk, Wv, bv, Wp, bp
    const float* x  = (const float*)d_in[0];
    const float* Wv = (const float*)d_in[5];
    const float* bv = (const float*)d_in[6];
    const float* Wp = (const float*)d_in[7];
    const float* bp = (const float*)d_in[8];
    float* out = (float*)d_out;

    __half *xh, *wph, *wpl, *wvth, *wvtl, *wch;
    cudaGetSymbolAddress((void**)&xh, g_xh);
    cudaGetSymbolAddress((void**)&wph, g_wph);
    cudaGetSymbolAddress((void**)&wpl, g_wpl);
    cudaGetSymbolAddress((void**)&wvth, g_wvth);
    cudaGetSymbolAddress((void**)&wvtl, g_wvtl);
    cudaGetSymbolAddress((void**)&wch, g_wch);

    cudaFuncSetAttribute(wc_gemm_kernel,
                         cudaFuncAttributeMaxDynamicSharedMemorySize, WSMEM_TOTAL);
    cudaFuncSetAttribute(main_gemm_kernel,
                         cudaFuncAttributeMaxDynamicSharedMemorySize, MSMEM_TOTAL);

    prep_kernel<<<1280, 256>>>(Wv, Wp, bv, bp, wvth, wvtl, wph, wpl);
    wc_gemm_kernel<<<dim3(8, 16), 256, WSMEM_TOTAL>>>(wph, wpl, wvth, wvtl, wch,
                                                      x, xh);
    main_gemm_kernel<<<dim3(8, 64), 128, MSMEM_TOTAL>>>(xh, wch, out);
}

// round 11
// speedup vs baseline: 1.2277x; 1.1171x over previous
#include <cuda_runtime.h>
#include <cuda_fp16.h>
#include <cstdint>

// ============================================================================
// Collapse (verified): out = 2048 * x @ (Wp@Wv)^T + (2048*Wp@bv + bp)
// fp16 HMMA path. Main GEMM measured at ~95% of the legacy mma.sync ceiling
// (1024 FLOP/cyc/SM model) -> frozen.
// R11: wc GEMM single fp16 product (was 3-product split). Error model:
//   measured 2.93e-4 already includes Wc fp16 STORAGE rounding; single-product
//   adds Wc accumulation error ~3.5e-4 -> total ~ sqrt(2.9^2+3.5^2)e-4 = 4.6e-4
//   < 1e-3 gate. wc MMAs /3, prep stores /2 (wpl/wvtl dead).
// ============================================================================

#define KDIM 1024
#define MMAIN 8192
#define NMAIN 1024
#define BK 64

// ---- wc gemm: BM=64, BN=128, single product; stage = A 8KB | B 16KB
#define WBM 64
#define WBN 128
#define WSTAGES 3
#define WSTAGE_BYTES 24576
#define WSMEM_TOTAL (WSTAGES * WSTAGE_BYTES)   // 72 KB
// ---- main gemm: BM=BN=128, 1-product, 128 threads; stage = A|B = 32KB
#define MBM 128
#define MBN 128
#define MSTAGES 3
#define MSTAGE_BYTES 32768
#define MSMEM_TOTAL (MSTAGES * MSTAGE_BYTES)   // 96 KB -> 2 CTAs/SM

// -------------------- scratch -------------------------------------------------
__device__ __half g_xh[(size_t)MMAIN * KDIM];
__device__ __half g_wph[(size_t)KDIM * KDIM];
__device__ __half g_wvth[(size_t)KDIM * KDIM];
__device__ __half g_wch[(size_t)KDIM * KDIM];
__device__ float g_bcomb[KDIM];

// -------------------- helpers -------------------------------------------------
__device__ __forceinline__ uint32_t sptr(const void* p) {
    return (uint32_t)__cvta_generic_to_shared(p);
}
__device__ __forceinline__ void cp_async16(uint32_t smem, const void* gmem) {
    asm volatile("cp.async.cg.shared.global [%0], [%1], 16;"
                 :: "r"(smem), "l"(gmem) : "memory");
}
__device__ __forceinline__ void cp_commit() {
    asm volatile("cp.async.commit_group;" ::: "memory");
}
template <int N> __device__ __forceinline__ void cp_wait() {
    asm volatile("cp.async.wait_group %0;" :: "n"(N) : "memory");
}
__device__ __forceinline__ void ldmatrix4(uint32_t* r, uint32_t addr) {
    asm volatile("ldmatrix.sync.aligned.m8n8.x4.shared.b16 {%0,%1,%2,%3}, [%4];"
                 : "=r"(r[0]), "=r"(r[1]), "=r"(r[2]), "=r"(r[3]) : "r"(addr));
}
__device__ __forceinline__ void mma16816(float* c, const uint32_t* a,
                                         uint32_t b0, uint32_t b1) {
    asm volatile(
        "mma.sync.aligned.m16n8k16.row.col.f32.f16.f16.f32 "
        "{%0,%1,%2,%3}, {%4,%5,%6,%7}, {%8,%9}, {%0,%1,%2,%3};"
        : "+f"(c[0]), "+f"(c[1]), "+f"(c[2]), "+f"(c[3])
        : "r"(a[0]), "r"(a[1]), "r"(a[2]), "r"(a[3]), "r"(b0), "r"(b1));
}
__device__ __forceinline__ uint32_t swz(int row, int c) {
    return (uint32_t)(row * 128 + ((c ^ (row & 7)) << 4));
}

// -------------------- fused prep kernel ----------------------------------------
// grid = 1280 blocks x 256 threads:
//   [0, 1024)     : Wv transpose -> wvth (fp16), one 32x32 tile per block
//   [1024, 1152)  : Wp -> wph (fp16), 2048 float4 per block
//   [1152, 1280)  : bias_combine, 8 rows per block (warp per row)
__global__ __launch_bounds__(256) void prep_kernel(
    const float* __restrict__ Wv, const float* __restrict__ Wp,
    const float* __restrict__ bv, const float* __restrict__ bp,
    __half* __restrict__ wvth, __half* __restrict__ wph)
{
    __shared__ float t[32][33];
    int b = blockIdx.x;
    int tid = threadIdx.x;

    if (b < 1024) {
        int bx = (b & 31) * 32;    // n base
        int by = (b >> 5) * 32;    // k base
        int tx = tid & 31, ty = tid >> 5;
#pragma unroll
        for (int i = 0; i < 32; i += 8)
            t[ty + i][tx] = Wv[(size_t)(by + ty + i) * KDIM + bx + tx];
        __syncthreads();
#pragma unroll
        for (int i = 0; i < 32; i += 8) {
            float v = t[tx][ty + i];
            wvth[(size_t)(bx + ty + i) * KDIM + by + tx] = __float2half_rn(v);
        }
    } else if (b < 1152) {
        int blk = b - 1024;
#pragma unroll
        for (int i = 0; i < 8; i++) {
            size_t idx = (size_t)blk * 2048 + i * 256 + tid;
            float4 v = *(const float4*)(Wp + idx * 4);
            __half2 h0 = __floats2half2_rn(v.x, v.y);
            __half2 h1 = __floats2half2_rn(v.z, v.w);
            uint2 pk;
            pk.x = *reinterpret_cast<uint32_t*>(&h0);
            pk.y = *reinterpret_cast<uint32_t*>(&h1);
            *reinterpret_cast<uint2*>(wph + idx * 4) = pk;
        }
    } else {
        int row = (b - 1152) * 8 + (tid >> 5);
        int lane = tid & 31;
        float s = 0.f;
        for (int j = lane * 4; j < KDIM; j += 128) {
            float4 w = *(const float4*)(Wp + (size_t)row * KDIM + j);
            float4 bb = *(const float4*)(bv + j);
            s += w.x * bb.x + w.y * bb.y + w.z * bb.z + w.w * bb.w;
        }
#pragma unroll
        for (int o = 16; o > 0; o >>= 1) s += __shfl_xor_sync(0xffffffff, s, o);
        if (lane == 0) g_bcomb[row] = 2048.0f * s + bp[row];
    }
}

// -------------------- wc GEMM: single fp16 product (+ x conversion) ------------
// Wc = Wp @ Wv; A = wph [1024,1024], B = wvth [1024,1024] (NT).
// Each CTA also converts a 65536-float slice of x to fp16 interleaved with
// the k-loop (LDGs before MMA block, cvt+STG after).
__global__ __launch_bounds__(256, 1) void wc_gemm_kernel(
    const __half* __restrict__ Ah, const __half* __restrict__ Bh,
    __half* __restrict__ Ch,
    const float* __restrict__ Xsrc, __half* __restrict__ Xdst)
{
    extern __shared__ char smem[];
    const uint32_t sbase = sptr(smem);
    const int tid = threadIdx.x;
    const int wid = tid >> 5, lane = tid & 31;
    const int wm = wid & 1, wn = wid >> 1;
    const int bm = blockIdx.y * WBM, bn = blockIdx.x * WBN;
    const int cta = blockIdx.y * gridDim.x + blockIdx.x;   // 0..127
    const size_t xbase = (size_t)cta * 16384;              // float4 units

    float acc[2][4][4];
#pragma unroll
    for (int i = 0; i < 2; i++)
#pragma unroll
        for (int j = 0; j < 4; j++)
#pragma unroll
            for (int q = 0; q < 4; q++) acc[i][j][q] = 0.f;

    // stage: [A 8K | B 16K]
    auto load_stage = [&](int t, int s) {
        uint32_t st = sbase + s * WSTAGE_BYTES;
        int kcol = t * BK;
#pragma unroll
        for (int i = 0; i < 2; i++) {
            int chunk = tid + i * 256;
            int r = chunk >> 3, c = chunk & 7;
            cp_async16(st + swz(r, c), Ah + (size_t)(bm + r) * KDIM + kcol + c * 8);
        }
#pragma unroll
        for (int i = 0; i < 4; i++) {
            int chunk = tid + i * 256;
            int r = chunk >> 3, c = chunk & 7;
            cp_async16(st + 8192 + swz(r, c),
                       Bh + (size_t)(bn + r) * KDIM + kcol + c * 8);
        }
    };

    const int NT = KDIM / BK;  // 16
#pragma unroll
    for (int t = 0; t < WSTAGES - 1; t++) { load_stage(t, t); cp_commit(); }

    const int lrow = (lane & 7) + ((lane >> 3) & 1) * 8;
    const int lcol = lane >> 4;

    for (int kt = 0; kt < NT; kt++) {
        cp_wait<WSTAGES - 2>();
        __syncthreads();
        if (kt + WSTAGES - 1 < NT)
            load_stage(kt + WSTAGES - 1, (kt + WSTAGES - 1) % WSTAGES);
        cp_commit();

        // x conversion: issue LDGs, hide latency under MMAs
        float4 xv[4];
        size_t xo = xbase + (size_t)kt * 1024 + tid;
#pragma unroll
        for (int i = 0; i < 4; i++)
            xv[i] = __ldg((const float4*)Xsrc + xo + i * 256);

        uint32_t sa = sbase + (kt % WSTAGES) * WSTAGE_BYTES;
        uint32_t sb = sa + 8192;

#pragma unroll
        for (int s = 0; s < BK / 16; s++) {
            uint32_t ah[2][4], bh[2][4];
#pragma unroll
            for (int im = 0; im < 2; im++)
                ldmatrix4(ah[im], sa + swz(wm * 32 + im * 16 + lrow,
                                           s * 2 + lcol));
#pragma unroll
            for (int jn = 0; jn < 2; jn++)
                ldmatrix4(bh[jn], sb + swz(wn * 32 + jn * 16 + lrow,
                                           s * 2 + lcol));
#pragma unroll
            for (int im = 0; im < 2; im++)
#pragma unroll
                for (int n8 = 0; n8 < 4; n8++) {
                    int jn = n8 >> 1, h = n8 & 1;
                    mma16816(acc[im][n8], ah[im], bh[jn][h], bh[jn][h + 2]);
                }
        }

        // x conversion: cvt + store
#pragma unroll
        for (int i = 0; i < 4; i++) {
            __half2 h0 = __floats2half2_rn(xv[i].x, xv[i].y);
            __half2 h1 = __floats2half2_rn(xv[i].z, xv[i].w);
            uint2 pk;
            pk.x = *reinterpret_cast<uint32_t*>(&h0);
            pk.y = *reinterpret_cast<uint32_t*>(&h1);
            *reinterpret_cast<uint2*>(Xdst + (xo + i * 256) * 4) = pk;
        }
    }

    const int qr = lane >> 2, qc = lane & 3;
#pragma unroll
    for (int im = 0; im < 2; im++) {
        int m0 = bm + wm * 32 + im * 16 + qr;
#pragma unroll
        for (int n8 = 0; n8 < 4; n8++) {
            int n0 = bn + wn * 32 + n8 * 8 + qc * 2;
            float* c = acc[im][n8];
#pragma unroll
            for (int q = 0; q < 4; q++) {
                int m = m0 + (q >> 1) * 8;
                int n = n0 + (q & 1);
                Ch[(size_t)m * KDIM + n] = __float2half_rn(c[q]);
            }
        }
    }
}

// -------------------- main GEMM: 128x128 CTA, 4 warps of 64x64, 2 CTA/SM ------
__global__ __launch_bounds__(128, 2) void main_gemm_kernel(
    const __half* __restrict__ A, const __half* __restrict__ B,
    float* __restrict__ Cout)
{
    extern __shared__ char smem[];
    const uint32_t sbase = sptr(smem);
    const int tid = threadIdx.x;
    const int wid = tid >> 5, lane = tid & 31;
    const int wm = wid & 1;
    const int wn = wid >> 1;
    const int bm = blockIdx.y * MBM, bn = blockIdx.x * MBN;

    float acc[4][8][4];
#pragma unroll
    for (int i = 0; i < 4; i++)
#pragma unroll
        for (int j = 0; j < 8; j++)
#pragma unroll
            for (int q = 0; q < 4; q++) acc[i][j][q] = 0.f;

    auto load_stage = [&](int t, int s) {
        uint32_t sa = sbase + s * MSTAGE_BYTES;
        uint32_t sb = sa + 16384;
        int kcol = t * BK;
#pragma unroll
        for (int i = 0; i < 8; i++) {
            int chunk = tid + i * 128;
            int r = chunk >> 3, c = chunk & 7;
            uint32_t sw = swz(r, c);
            cp_async16(sa + sw, A + (size_t)(bm + r) * KDIM + kcol + c * 8);
            cp_async16(sb + sw, B + (size_t)(bn + r) * KDIM + kcol + c * 8);
        }
    };

    const int NT = KDIM / BK;  // 16
#pragma unroll
    for (int t = 0; t < MSTAGES - 1; t++) { load_stage(t, t); cp_commit(); }

    const int lrow = (lane & 7) + ((lane >> 3) & 1) * 8;
    const int lcol = lane >> 4;

    for (int kt = 0; kt < NT; kt++) {
        cp_wait<MSTAGES - 2>();
        __syncthreads();
        if (kt + MSTAGES - 1 < NT)
            load_stage(kt + MSTAGES - 1, (kt + MSTAGES - 1) % MSTAGES);
        cp_commit();

        uint32_t sa = sbase + (kt % MSTAGES) * MSTAGE_BYTES;
        uint32_t sb = sa + 16384;

#pragma unroll
        for (int s = 0; s < BK / 16; s++) {
            uint32_t af[4][4], bf[4][4];
#pragma unroll
            for (int im = 0; im < 4; im++)
                ldmatrix4(af[im], sa + swz(wm * 64 + im * 16 + lrow,
                                           s * 2 + lcol));
#pragma unroll
            for (int jn = 0; jn < 4; jn++)
                ldmatrix4(bf[jn], sb + swz(wn * 64 + jn * 16 + lrow,
                                           s * 2 + lcol));
#pragma unroll
            for (int im = 0; im < 4; im++)
#pragma unroll
                for (int n8 = 0; n8 < 8; n8++) {
                    int jn = n8 >> 1, h = n8 & 1;
                    mma16816(acc[im][n8], af[im], bf[jn][h], bf[jn][h + 2]);
                }
        }
    }

    const int qr = lane >> 2, qc = lane & 3;
#pragma unroll
    for (int im = 0; im < 4; im++) {
        int m0 = bm + wm * 64 + im * 16 + qr;
#pragma unroll
        for (int n8 = 0; n8 < 8; n8++) {
            int n0 = bn + wn * 64 + n8 * 8 + qc * 2;
            float* c = acc[im][n8];
            float b0 = g_bcomb[n0], b1 = g_bcomb[n0 + 1];
            *(float2*)(Cout + (size_t)m0 * NMAIN + n0) =
                make_float2(2048.f * c[0] + b0, 2048.f * c[1] + b1);
            *(float2*)(Cout + (size_t)(m0 + 8) * NMAIN + n0) =
                make_float2(2048.f * c[2] + b0, 2048.f * c[3] + b1);
        }
    }
}

// -------------------- host ------------------------------------------------------
extern "C" void kernel_launch(void* const* d_in, const int* in_sizes, int n_in,
                              void* d_out, int out_size)
{
    // metadata order: x, Wq, bq, Wk, bk, Wv, bv, Wp, bp
    const float* x  = (const float*)d_in[0];
    const float* Wv = (const float*)d_in[5];
    const float* bv = (const float*)d_in[6];
    const float* Wp = (const float*)d_in[7];
    const float* bp = (const float*)d_in[8];
    float* out = (float*)d_out;

    __half *xh, *wph, *wvth, *wch;
    cudaGetSymbolAddress((void**)&xh, g_xh);
    cudaGetSymbolAddress((void**)&wph, g_wph);
    cudaGetSymbolAddress((void**)&wvth, g_wvth);
    cudaGetSymbolAddress((void**)&wch, g_wch);

    cudaFuncSetAttribute(wc_gemm_kernel,
                         cudaFuncAttributeMaxDynamicSharedMemorySize, WSMEM_TOTAL);
    cudaFuncSetAttribute(main_gemm_kernel,
                         cudaFuncAttributeMaxDynamicSharedMemorySize, MSMEM_TOTAL);

    prep_kernel<<<1280, 256>>>(Wv, Wp, bv, bp, wvth, wph);
    wc_gemm_kernel<<<dim3(8, 16), 256, WSMEM_TOTAL>>>(wph, wvth, wch, x, xh);
    main_gemm_kernel<<<dim3(8, 64), 128, MSMEM_TOTAL>>>(xh, wch, out);
}

// round 12
// speedup vs baseline: 1.2313x; 1.0029x over previous
#include <cuda_runtime.h>
#include <cuda_fp16.h>
#include <cstdint>

// ============================================================================
// Collapse (verified): out = 2048 * x @ (Wp@Wv)^T + (2048*Wp@bv + bp)
// fp16 HMMA path. rel_err 4.15e-4 (single-product wc, R11).
// R12: prep was latency-bound (issue 13.6%, HBM 12.5%): Wv transpose used
//   scalar loads/stores. Retile to 32k x 128n blocks: float4 loads, packed
//   uint4 (8 x half) stores, smem pad 133 for conflict-free column reads.
//   wc + main GEMM frozen (wc at 128-CTA tensor floor, main at HMMA floor).
// ============================================================================

#define KDIM 1024
#define MMAIN 8192
#define NMAIN 1024
#define BK 64

// ---- wc gemm: BM=64, BN=128, single product; stage = A 8KB | B 16KB
#define WBM 64
#define WBN 128
#define WSTAGES 3
#define WSTAGE_BYTES 24576
#define WSMEM_TOTAL (WSTAGES * WSTAGE_BYTES)   // 72 KB
// ---- main gemm: BM=BN=128, 1-product, 128 threads; stage = A|B = 32KB
#define MBM 128
#define MBN 128
#define MSTAGES 3
#define MSTAGE_BYTES 32768
#define MSMEM_TOTAL (MSTAGES * MSTAGE_BYTES)   // 96 KB -> 2 CTAs/SM

// -------------------- scratch -------------------------------------------------
__device__ __half g_xh[(size_t)MMAIN * KDIM];
__device__ __half g_wph[(size_t)KDIM * KDIM];
__device__ __half g_wvth[(size_t)KDIM * KDIM];
__device__ __half g_wch[(size_t)KDIM * KDIM];
__device__ float g_bcomb[KDIM];

// -------------------- helpers -------------------------------------------------
__device__ __forceinline__ uint32_t sptr(const void* p) {
    return (uint32_t)__cvta_generic_to_shared(p);
}
__device__ __forceinline__ void cp_async16(uint32_t smem, const void* gmem) {
    asm volatile("cp.async.cg.shared.global [%0], [%1], 16;"
                 :: "r"(smem), "l"(gmem) : "memory");
}
__device__ __forceinline__ void cp_commit() {
    asm volatile("cp.async.commit_group;" ::: "memory");
}
template <int N> __device__ __forceinline__ void cp_wait() {
    asm volatile("cp.async.wait_group %0;" :: "n"(N) : "memory");
}
__device__ __forceinline__ void ldmatrix4(uint32_t* r, uint32_t addr) {
    asm volatile("ldmatrix.sync.aligned.m8n8.x4.shared.b16 {%0,%1,%2,%3}, [%4];"
                 : "=r"(r[0]), "=r"(r[1]), "=r"(r[2]), "=r"(r[3]) : "r"(addr));
}
__device__ __forceinline__ void mma16816(float* c, const uint32_t* a,
                                         uint32_t b0, uint32_t b1) {
    asm volatile(
        "mma.sync.aligned.m16n8k16.row.col.f32.f16.f16.f32 "
        "{%0,%1,%2,%3}, {%4,%5,%6,%7}, {%8,%9}, {%0,%1,%2,%3};"
        : "+f"(c[0]), "+f"(c[1]), "+f"(c[2]), "+f"(c[3])
        : "r"(a[0]), "r"(a[1]), "r"(a[2]), "r"(a[3]), "r"(b0), "r"(b1));
}
__device__ __forceinline__ uint32_t swz(int row, int c) {
    return (uint32_t)(row * 128 + ((c ^ (row & 7)) << 4));
}

// -------------------- fused prep kernel ----------------------------------------
// grid = 512 blocks x 256 threads:
//   [0, 256)   : Wv transpose -> wvth (fp16); block = 32k x 128n tile,
//                float4 loads, uint4 (8 half) stores
//   [256, 384) : Wp -> wph (fp16), 2048 float4 per block
//   [384, 512) : bias_combine, 8 rows per block (warp per row)
__global__ __launch_bounds__(256) void prep_kernel(
    const float* __restrict__ Wv, const float* __restrict__ Wp,
    const float* __restrict__ bv, const float* __restrict__ bp,
    __half* __restrict__ wvth, __half* __restrict__ wph)
{
    __shared__ float t[32][133];   // pad 133: column reads hit distinct banks
    int b = blockIdx.x;
    int tid = threadIdx.x;

    if (b < 256) {
        // tile: k rows [by, by+32), n cols [bx, bx+128)
        int bx = (b & 7) * 128;
        int by = (b >> 3) * 32;
        // load 32 x 128 floats as float4 (coalesced 16B/thread/iter)
#pragma unroll
        for (int i = 0; i < 4; i++) {
            int f4 = tid + i * 256;          // 0..1023
            int r = f4 >> 5, c4 = f4 & 31;   // row, float4-col
            float4 v = *(const float4*)(Wv + (size_t)(by + r) * KDIM + bx + c4 * 4);
            t[r][c4 * 4 + 0] = v.x;
            t[r][c4 * 4 + 1] = v.y;
            t[r][c4 * 4 + 2] = v.z;
            t[r][c4 * 4 + 3] = v.w;
        }
        __syncthreads();
        // write transposed: wvth[n][k], 8 halves (16B) per task
#pragma unroll
        for (int i = 0; i < 2; i++) {
            int task = tid + i * 256;        // 0..511
            int nl = task >> 2;              // n within tile (0..127)
            int kb = (task & 3) * 8;         // k seg
            __half2 h[4];
#pragma unroll
            for (int j = 0; j < 4; j++)
                h[j] = __floats2half2_rn(t[kb + 2 * j][nl], t[kb + 2 * j + 1][nl]);
            uint4 pk;
            pk.x = *reinterpret_cast<uint32_t*>(&h[0]);
            pk.y = *reinterpret_cast<uint32_t*>(&h[1]);
            pk.z = *reinterpret_cast<uint32_t*>(&h[2]);
            pk.w = *reinterpret_cast<uint32_t*>(&h[3]);
            *reinterpret_cast<uint4*>(wvth + (size_t)(bx + nl) * KDIM + by + kb) = pk;
        }
    } else if (b < 384) {
        int blk = b - 256;
#pragma unroll
        for (int i = 0; i < 8; i++) {
            size_t idx = (size_t)blk * 2048 + i * 256 + tid;
            float4 v = *(const float4*)(Wp + idx * 4);
            __half2 h0 = __floats2half2_rn(v.x, v.y);
            __half2 h1 = __floats2half2_rn(v.z, v.w);
            uint2 pk;
            pk.x = *reinterpret_cast<uint32_t*>(&h0);
            pk.y = *reinterpret_cast<uint32_t*>(&h1);
            *reinterpret_cast<uint2*>(wph + idx * 4) = pk;
        }
    } else {
        int row = (b - 384) * 8 + (tid >> 5);
        int lane = tid & 31;
        float s = 0.f;
        for (int j = lane * 4; j < KDIM; j += 128) {
            float4 w = *(const float4*)(Wp + (size_t)row * KDIM + j);
            float4 bb = *(const float4*)(bv + j);
            s += w.x * bb.x + w.y * bb.y + w.z * bb.z + w.w * bb.w;
        }
#pragma unroll
        for (int o = 16; o > 0; o >>= 1) s += __shfl_xor_sync(0xffffffff, s, o);
        if (lane == 0) g_bcomb[row] = 2048.0f * s + bp[row];
    }
}

// -------------------- wc GEMM: single fp16 product (+ x conversion) ------------
__global__ __launch_bounds__(256, 1) void wc_gemm_kernel(
    const __half* __restrict__ Ah, const __half* __restrict__ Bh,
    __half* __restrict__ Ch,
    const float* __restrict__ Xsrc, __half* __restrict__ Xdst)
{
    extern __shared__ char smem[];
    const uint32_t sbase = sptr(smem);
    const int tid = threadIdx.x;
    const int wid = tid >> 5, lane = tid & 31;
    const int wm = wid & 1, wn = wid >> 1;
    const int bm = blockIdx.y * WBM, bn = blockIdx.x * WBN;
    const int cta = blockIdx.y * gridDim.x + blockIdx.x;   // 0..127
    const size_t xbase = (size_t)cta * 16384;              // float4 units

    float acc[2][4][4];
#pragma unroll
    for (int i = 0; i < 2; i++)
#pragma unroll
        for (int j = 0; j < 4; j++)
#pragma unroll
            for (int q = 0; q < 4; q++) acc[i][j][q] = 0.f;

    auto load_stage = [&](int t, int s) {
        uint32_t st = sbase + s * WSTAGE_BYTES;
        int kcol = t * BK;
#pragma unroll
        for (int i = 0; i < 2; i++) {
            int chunk = tid + i * 256;
            int r = chunk >> 3, c = chunk & 7;
            cp_async16(st + swz(r, c), Ah + (size_t)(bm + r) * KDIM + kcol + c * 8);
        }
#pragma unroll
        for (int i = 0; i < 4; i++) {
            int chunk = tid + i * 256;
            int r = chunk >> 3, c = chunk & 7;
            cp_async16(st + 8192 + swz(r, c),
                       Bh + (size_t)(bn + r) * KDIM + kcol + c * 8);
        }
    };

    const int NT = KDIM / BK;  // 16
#pragma unroll
    for (int t = 0; t < WSTAGES - 1; t++) { load_stage(t, t); cp_commit(); }

    const int lrow = (lane & 7) + ((lane >> 3) & 1) * 8;
    const int lcol = lane >> 4;

    for (int kt = 0; kt < NT; kt++) {
        cp_wait<WSTAGES - 2>();
        __syncthreads();
        if (kt + WSTAGES - 1 < NT)
            load_stage(kt + WSTAGES - 1, (kt + WSTAGES - 1) % WSTAGES);
        cp_commit();

        float4 xv[4];
        size_t xo = xbase + (size_t)kt * 1024 + tid;
#pragma unroll
        for (int i = 0; i < 4; i++)
            xv[i] = __ldg((const float4*)Xsrc + xo + i * 256);

        uint32_t sa = sbase + (kt % WSTAGES) * WSTAGE_BYTES;
        uint32_t sb = sa + 8192;

#pragma unroll
        for (int s = 0; s < BK / 16; s++) {
            uint32_t ah[2][4], bh[2][4];
#pragma unroll
            for (int im = 0; im < 2; im++)
                ldmatrix4(ah[im], sa + swz(wm * 32 + im * 16 + lrow,
                                           s * 2 + lcol));
#pragma unroll
            for (int jn = 0; jn < 2; jn++)
                ldmatrix4(bh[jn], sb + swz(wn * 32 + jn * 16 + lrow,
                                           s * 2 + lcol));
#pragma unroll
            for (int im = 0; im < 2; im++)
#pragma unroll
                for (int n8 = 0; n8 < 4; n8++) {
                    int jn = n8 >> 1, h = n8 & 1;
                    mma16816(acc[im][n8], ah[im], bh[jn][h], bh[jn][h + 2]);
                }
        }

#pragma unroll
        for (int i = 0; i < 4; i++) {
            __half2 h0 = __floats2half2_rn(xv[i].x, xv[i].y);
            __half2 h1 = __floats2half2_rn(xv[i].z, xv[i].w);
            uint2 pk;
            pk.x = *reinterpret_cast<uint32_t*>(&h0);
            pk.y = *reinterpret_cast<uint32_t*>(&h1);
            *reinterpret_cast<uint2*>(Xdst + (xo + i * 256) * 4) = pk;
        }
    }

    const int qr = lane >> 2, qc = lane & 3;
#pragma unroll
    for (int im = 0; im < 2; im++) {
        int m0 = bm + wm * 32 + im * 16 + qr;
#pragma unroll
        for (int n8 = 0; n8 < 4; n8++) {
            int n0 = bn + wn * 32 + n8 * 8 + qc * 2;
            float* c = acc[im][n8];
#pragma unroll
            for (int q = 0; q < 4; q++) {
                int m = m0 + (q >> 1) * 8;
                int n = n0 + (q & 1);
                Ch[(size_t)m * KDIM + n] = __float2half_rn(c[q]);
            }
        }
    }
}

// -------------------- main GEMM: 128x128 CTA, 4 warps of 64x64, 2 CTA/SM ------
__global__ __launch_bounds__(128, 2) void main_gemm_kernel(
    const __half* __restrict__ A, const __half* __restrict__ B,
    float* __restrict__ Cout)
{
    extern __shared__ char smem[];
    const uint32_t sbase = sptr(smem);
    const int tid = threadIdx.x;
    const int wid = tid >> 5, lane = tid & 31;
    const int wm = wid & 1;
    const int wn = wid >> 1;
    const int bm = blockIdx.y * MBM, bn = blockIdx.x * MBN;

    float acc[4][8][4];
#pragma unroll
    for (int i = 0; i < 4; i++)
#pragma unroll
        for (int j = 0; j < 8; j++)
#pragma unroll
            for (int q = 0; q < 4; q++) acc[i][j][q] = 0.f;

    auto load_stage = [&](int t, int s) {
        uint32_t sa = sbase + s * MSTAGE_BYTES;
        uint32_t sb = sa + 16384;
        int kcol = t * BK;
#pragma unroll
        for (int i = 0; i < 8; i++) {
            int chunk = tid + i * 128;
            int r = chunk >> 3, c = chunk & 7;
            uint32_t sw = swz(r, c);
            cp_async16(sa + sw, A + (size_t)(bm + r) * KDIM + kcol + c * 8);
            cp_async16(sb + sw, B + (size_t)(bn + r) * KDIM + kcol + c * 8);
        }
    };

    const int NT = KDIM / BK;  // 16
#pragma unroll
    for (int t = 0; t < MSTAGES - 1; t++) { load_stage(t, t); cp_commit(); }

    const int lrow = (lane & 7) + ((lane >> 3) & 1) * 8;
    const int lcol = lane >> 4;

    for (int kt = 0; kt < NT; kt++) {
        cp_wait<MSTAGES - 2>();
        __syncthreads();
        if (kt + MSTAGES - 1 < NT)
            load_stage(kt + MSTAGES - 1, (kt + MSTAGES - 1) % MSTAGES);
        cp_commit();

        uint32_t sa = sbase + (kt % MSTAGES) * MSTAGE_BYTES;
        uint32_t sb = sa + 16384;

#pragma unroll
        for (int s = 0; s < BK / 16; s++) {
            uint32_t af[4][4], bf[4][4];
#pragma unroll
            for (int im = 0; im < 4; im++)
                ldmatrix4(af[im], sa + swz(wm * 64 + im * 16 + lrow,
                                           s * 2 + lcol));
#pragma unroll
            for (int jn = 0; jn < 4; jn++)
                ldmatrix4(bf[jn], sb + swz(wn * 64 + jn * 16 + lrow,
                                           s * 2 + lcol));
#pragma unroll
            for (int im = 0; im < 4; im++)
#pragma unroll
                for (int n8 = 0; n8 < 8; n8++) {
                    int jn = n8 >> 1, h = n8 & 1;
                    mma16816(acc[im][n8], af[im], bf[jn][h], bf[jn][h + 2]);
                }
        }
    }

    const int qr = lane >> 2, qc = lane & 3;
#pragma unroll
    for (int im = 0; im < 4; im++) {
        int m0 = bm + wm * 64 + im * 16 + qr;
#pragma unroll
        for (int n8 = 0; n8 < 8; n8++) {
            int n0 = bn + wn * 64 + n8 * 8 + qc * 2;
            float* c = acc[im][n8];
            float b0 = g_bcomb[n0], b1 = g_bcomb[n0 + 1];
            *(float2*)(Cout + (size_t)m0 * NMAIN + n0) =
                make_float2(2048.f * c[0] + b0, 2048.f * c[1] + b1);
            *(float2*)(Cout + (size_t)(m0 + 8) * NMAIN + n0) =
                make_float2(2048.f * c[2] + b0, 2048.f * c[3] + b1);
        }
    }
}

// -------------------- host ------------------------------------------------------
extern "C" void kernel_launch(void* const* d_in, const int* in_sizes, int n_in,
                              void* d_out, int out_size)
{
    // metadata order: x, Wq, bq, Wk, bk, Wv, bv, Wp, bp
    const float* x  = (const float*)d_in[0];
    const float* Wv = (const float*)d_in[5];
    const float* bv = (const float*)d_in[6];
    const float* Wp = (const float*)d_in[7];
    const float* bp = (const float*)d_in[8];
    float* out = (float*)d_out;

    __half *xh, *wph, *wvth, *wch;
    cudaGetSymbolAddress((void**)&xh, g_xh);
    cudaGetSymbolAddress((void**)&wph, g_wph);
    cudaGetSymbolAddress((void**)&wvth, g_wvth);
    cudaGetSymbolAddress((void**)&wch, g_wch);

    cudaFuncSetAttribute(wc_gemm_kernel,
                         cudaFuncAttributeMaxDynamicSharedMemorySize, WSMEM_TOTAL);
    cudaFuncSetAttribute(main_gemm_kernel,
                         cudaFuncAttributeMaxDynamicSharedMemorySize, MSMEM_TOTAL);

    prep_kernel<<<512, 256>>>(Wv, Wp, bv, bp, wvth, wph);
    wc_gemm_kernel<<<dim3(8, 16), 256, WSMEM_TOTAL>>>(wph, wvth, wch, x, xh);
    main_gemm_kernel<<<dim3(8, 64), 128, MSMEM_TOTAL>>>(xh, wch, out);
}